// round 10
// baseline (speedup 1.0000x reference)
#include <cuda_runtime.h>
#include <cuda_fp16.h>
#include <math.h>
#include <stdint.h>

#define HDIM 128
#define MAXM 1000
#define MAXJ 5000
#define MAXN 200000
#define TILE_OPS 128
#define MAXP 12800            // max partials = tiles*8

#define RTH2  512

// ------------------------------ scratch ------------------------------------
__device__ __align__(16) float  g_g[HDIM];
__device__ __align__(16) __half g_Ah[MAXM * HDIM];   // fp16 A rows (no g term)
__device__ __align__(16) __half g_Bh[MAXJ * HDIM];   // fp16 B rows
__device__ float  g_pmax[MAXP];
__device__ int    g_pidx[MAXP];
__device__ double g_pZ[MAXP];
__device__ double g_pS1[MAXP];
// W1^T (rows = output h, cols = k), fp16, blocked-SW128 layout (32KB).
__device__ __align__(16) unsigned char g_W1T[32768];

// --------------------------- helpers ---------------------------------------
__device__ __forceinline__ uint32_t smem_u32(const void* p) {
    uint32_t a;
    asm("{ .reg .u64 t; cvta.to.shared.u64 t, %1; cvt.u32.u64 %0, t; }"
        : "=r"(a) : "l"(p));
    return a;
}

// swizzled byte offset in a 128row x 128col fp16 blocked-SW128 tile
__device__ __forceinline__ uint32_t tile_off(int row, int col) {
    uint32_t off = (uint32_t)(((row >> 3) + ((col >> 6) << 4)) * 1024
                              + (row & 7) * 128 + (col & 63) * 2);
    return off ^ ((off >> 3) & 0x70);
}

__device__ __forceinline__ void ldsm4(uint32_t* r, uint32_t addr) {
    asm volatile("ldmatrix.sync.aligned.m8n8.x4.shared.b16 {%0,%1,%2,%3}, [%4];"
                 : "=r"(r[0]), "=r"(r[1]), "=r"(r[2]), "=r"(r[3]) : "r"(addr));
}
__device__ __forceinline__ void mma_f16(float* d, const uint32_t* a,
                                        uint32_t b0, uint32_t b1) {
    asm volatile("mma.sync.aligned.m16n8k16.row.col.f32.f16.f16.f32 "
                 "{%0,%1,%2,%3}, {%4,%5,%6,%7}, {%8,%9}, {%0,%1,%2,%3};"
                 : "+f"(d[0]), "+f"(d[1]), "+f"(d[2]), "+f"(d[3])
                 : "r"(a[0]), "r"(a[1]), "r"(a[2]), "r"(a[3]), "r"(b0), "r"(b1));
}

// ---------------------------------------------------------------------------
// Kernel P: merged prep.  128 threads/block.  Block roles:
//   r <  M           : A[m] = x_m[m] @ W0[2H:3H]          (fp16, NO g term)
//   r <  M+J         : B[j] = x_job[j] @ W0[3H:4H]        (fp16)
//   r == M+J         : g[h] = b0[h] + x_graph @ W0[:2H]   (fp32)
//   else (128 blocks): W1^T -> fp16 blocked-SW128
// ---------------------------------------------------------------------------
__global__ void __launch_bounds__(HDIM)
kern_prep(const float* __restrict__ x_graph,
          const float* __restrict__ x_m,
          const float* __restrict__ x_job,
          const float* __restrict__ W0,
          const float* __restrict__ b0,
          const float* __restrict__ W1,
          int M, int J)
{
    __shared__ float xs[2 * HDIM];
    int h = threadIdx.x;
    int r = blockIdx.x;

    if (r < M + J) {
        const float* src; const float* w; __half* dst;
        if (r < M) {
            src = x_m + (size_t)r * HDIM;
            w   = W0 + (size_t)(2 * HDIM) * HDIM;
            dst = g_Ah + (size_t)r * HDIM;
        } else {
            int j = r - M;
            src = x_job + (size_t)j * HDIM;
            w   = W0 + (size_t)(3 * HDIM) * HDIM;
            dst = g_Bh + (size_t)j * HDIM;
        }
        xs[h] = src[h];
        __syncthreads();
        float acc = 0.0f;
        #pragma unroll 8
        for (int k = 0; k < HDIM; ++k)
            acc = fmaf(xs[k], w[k * HDIM + h], acc);
        dst[h] = __float2half(acc);
    } else if (r == M + J) {
        xs[h] = x_graph[h];
        xs[h + HDIM] = x_graph[h + HDIM];
        __syncthreads();
        float acc = b0[h];
        #pragma unroll 8
        for (int k = 0; k < 2 * HDIM; ++k)
            acc = fmaf(xs[k], W0[k * HDIM + h], acc);
        g_g[h] = acc;
    } else {
        int wb = r - (M + J + 1);              // 0..127
        int idx = wb * HDIM + h;               // 0..16383
        int rr = idx >> 7;
        int cc = idx & 127;
        float w = W1[cc * HDIM + rr];
        *(__half*)(g_W1T + tile_off(rr, cc)) = __float2half(w);
    }
}

// ---------------------------------------------------------------------------
// Kernel 2: fp16 HMMA tile kernel (R7 mainloop) + sync-free warp softmax
// partials.  128 ops/block, 256 threads (8 warps); warp w owns rows
// [w*16, w*16+16) x all 128 cols.
// D = h0 @ W1^T (fp32 accum);  score = b2 + sum_h relu(b1+D)*W2
// Each warp emits (max, argmax, Z, S1) for its 16 rows.
// ---------------------------------------------------------------------------
#define OFF_A     0
#define OFF_W     32768
#define OFF_SB1   65536
#define OFF_SW2   66048
#define SMEM_TILE_TOTAL 66560

__global__ void __launch_bounds__(256, 2)
kern_tile(const int* __restrict__ m_ids,
          const int* __restrict__ job_idx,
          const float* __restrict__ b1,
          const float* __restrict__ W2,
          const float* __restrict__ b2,
          int n)
{
    extern __shared__ char smem[];
    uint32_t sb = smem_u32(smem);
    int tid = threadIdx.x;
    int wid = tid >> 5;
    int lid = tid & 31;
    int base = blockIdx.x * TILE_OPS;

    // ---- copy pre-swizzled W tile (32KB) ----
    {
        const uint4* src = (const uint4*)g_W1T;
        uint4* dst = (uint4*)(smem + OFF_W);
        #pragma unroll
        for (int i = 0; i < 8; ++i)
            dst[tid + 256 * i] = src[tid + 256 * i];
    }
    if (tid < HDIM) {
        ((float*)(smem + OFF_SB1))[tid] = b1[tid];
        ((float*)(smem + OFF_SW2))[tid] = W2[tid];
    }

    // ---- stage 1: gather h0 = relu(A[m]+B[j]+g) -> fp16 smem tile ----
    {
        int c0 = lid * 4;                 // this lane's 4 k-columns
        float4 gk = *(const float4*)(g_g + c0);
        uint32_t colpart = (uint32_t)(((c0 >> 6) << 4) * 1024 + (c0 & 63) * 2);
        #pragma unroll 4
        for (int i = 0; i < 16; ++i) {
            int t = wid * 16 + i;
            int op = base + t;
            int m = 0, j = 0;
            if (op < n) { m = m_ids[op]; j = job_idx[op]; }
            uint2 ua = *(const uint2*)(g_Ah + m * HDIM + c0);
            uint2 ub = *(const uint2*)(g_Bh + j * HDIM + c0);
            float2 a0 = __half22float2(*(const half2*)&ua.x);
            float2 a1 = __half22float2(*(const half2*)&ua.y);
            float2 b0f = __half22float2(*(const half2*)&ub.x);
            float2 b1f = __half22float2(*(const half2*)&ub.y);
            float v0 = fmaxf(a0.x + b0f.x + gk.x, 0.0f);
            float v1 = fmaxf(a0.y + b0f.y + gk.y, 0.0f);
            float v2 = fmaxf(a1.x + b1f.x + gk.z, 0.0f);
            float v3 = fmaxf(a1.y + b1f.y + gk.w, 0.0f);
            half2 r0 = __floats2half2_rn(v0, v1);
            half2 r1 = __floats2half2_rn(v2, v3);
            uint32_t off = colpart + (uint32_t)(((t >> 3) << 10) + (t & 7) * 128);
            uint32_t sw = off ^ ((off >> 3) & 0x70);
            uint2 pv;
            pv.x = *(const uint32_t*)&r0;
            pv.y = *(const uint32_t*)&r1;
            *(uint2*)(smem + OFF_A + sw) = pv;
        }
    }
    __syncthreads();

    // ---- mainloop: 8 k-chunks x 8 n-pairs (R7 structure, proven) ----
    float d[16][4];
    #pragma unroll
    for (int nc = 0; nc < 16; ++nc)
        #pragma unroll
        for (int q = 0; q < 4; ++q) d[nc][q] = 0.0f;

    int arow = wid * 16 + (lid & 15);              // A-frag lane row
    int acolh = (lid >> 4) * 8;                    // A-frag lane k-offset
    int brow_in = ((lid >> 4) << 3) + (lid & 7);   // B-frag lane n-offset
    int bcol = ((lid >> 3) & 1) * 8;               // B-frag lane k-offset

    #pragma unroll
    for (int kc = 0; kc < 8; ++kc) {
        int kbase = kc * 16;
        uint32_t a[4];
        ldsm4(a, sb + OFF_A + tile_off(arow, kbase + acolh));
        #pragma unroll
        for (int np = 0; np < 8; ++np) {
            uint32_t b[4];
            ldsm4(b, sb + OFF_W + tile_off(np * 16 + brow_in, kbase + bcol));
            mma_f16(d[2 * np],     a, b[0], b[1]);
            mma_f16(d[2 * np + 1], a, b[2], b[3]);
        }
    }

    // ---- epilogue: relu(+b1)*W2, butterfly col-reduce, warp softmax partial
    {
        const float* sb1 = (const float*)(smem + OFF_SB1);
        const float* sw2 = (const float*)(smem + OFF_SW2);
        int g = lid >> 2;
        int t4 = lid & 3;
        float s0 = 0.0f, s1 = 0.0f;
        #pragma unroll
        for (int nc = 0; nc < 16; ++nc) {
            int c0 = nc * 8 + 2 * t4;
            float bb0 = sb1[c0], bb1 = sb1[c0 + 1];
            float w0 = sw2[c0], w1 = sw2[c0 + 1];
            s0 = fmaf(fmaxf(d[nc][0] + bb0, 0.0f), w0, s0);
            s0 = fmaf(fmaxf(d[nc][1] + bb1, 0.0f), w1, s0);
            s1 = fmaf(fmaxf(d[nc][2] + bb0, 0.0f), w0, s1);
            s1 = fmaf(fmaxf(d[nc][3] + bb1, 0.0f), w1, s1);
        }
        unsigned mask = 0xffffffffu;
        s0 += __shfl_xor_sync(mask, s0, 1);
        s0 += __shfl_xor_sync(mask, s0, 2);
        s1 += __shfl_xor_sync(mask, s1, 1);
        s1 += __shfl_xor_sync(mask, s1, 2);

        // warp softmax partial over this warp's 16 rows (t4==0 lanes hold them)
        float bias = b2[0];
        float sc0 = -INFINITY, sc1 = -INFINITY;
        int i0 = 0x7fffffff;
        if (t4 == 0) {
            int op0 = base + wid * 16 + g;
            int op1 = op0 + 8;
            if (op0 < n) { sc0 = s0 + bias; i0 = op0; }
            if (op1 < n) { sc1 = s1 + bias; }
        }
        // lane-local max (op0 < op1, strict > keeps first occurrence)
        float v = sc0; int bi = i0;
        if (sc1 > v) { v = sc1; bi = i0 + 8; }
        #pragma unroll
        for (int off = 16; off > 0; off >>= 1) {
            float vo = __shfl_xor_sync(mask, v, off);
            int io = __shfl_xor_sync(mask, bi, off);
            if (vo > v || (vo == v && io < bi)) { v = vo; bi = io; }
        }
        // v = warp max on all lanes
        float e0 = __expf(sc0 - v) * 0.0f + expf(sc0 - v);  // keep precise expf
        float e1 = expf(sc1 - v);
        double z = (double)e0 + (double)e1;
        double sd = 0.0;
        if (e0 > 0.0f) sd += (double)(sc0 - v) * (double)e0;
        if (e1 > 0.0f) sd += (double)(sc1 - v) * (double)e1;
        #pragma unroll
        for (int off = 16; off > 0; off >>= 1) {
            z  += __shfl_xor_sync(mask, z, off);
            sd += __shfl_xor_sync(mask, sd, off);
        }
        if (lid == 0) {
            int p = blockIdx.x * 8 + wid;
            g_pmax[p] = v;
            g_pidx[p] = bi;
            g_pZ[p]   = z;
            g_pS1[p]  = sd;
        }
    }
}

// ---------------------------------------------------------------------------
// Kernel 3: combine nblk partials (softmax-merge, fixed order -> deterministic)
// ---------------------------------------------------------------------------
__global__ void __launch_bounds__(RTH2)
kern_reduce(int nblk, float* __restrict__ out)
{
    __shared__ float  sv[RTH2];
    __shared__ int    si[RTH2];
    __shared__ double sz[RTH2];
    __shared__ double ss[RTH2];

    int tid = threadIdx.x;

    float best = -INFINITY;
    int bi = 0x7fffffff;
    for (int i = tid; i < nblk; i += RTH2) {
        float v = g_pmax[i];
        int io = g_pidx[i];
        if (v > best || (v == best && io < bi)) { best = v; bi = io; }
    }
    sv[tid] = best; si[tid] = bi;
    __syncthreads();
    for (int s = RTH2 / 2; s > 0; s >>= 1) {
        if (tid < s) {
            float vo = sv[tid + s]; int io = si[tid + s];
            if (vo > sv[tid] || (vo == sv[tid] && io < si[tid])) {
                sv[tid] = vo; si[tid] = io;
            }
        }
        __syncthreads();
    }
    float mx = sv[0];
    int idx = si[0];
    __syncthreads();

    double z = 0.0, s1 = 0.0;
    for (int i = tid; i < nblk; i += RTH2) {
        double zb = g_pZ[i];
        if (zb > 0.0) {
            double dd = (double)g_pmax[i] - (double)mx;
            double w = exp(dd);
            z  += w * zb;
            s1 += w * (g_pS1[i] + dd * zb);
        }
    }
    sz[tid] = z; ss[tid] = s1;
    __syncthreads();
    for (int s = RTH2 / 2; s > 0; s >>= 1) {
        if (tid < s) { sz[tid] += sz[tid + s]; ss[tid] += ss[tid + s]; }
        __syncthreads();
    }
    if (tid == 0) {
        double Z = sz[0], S1 = ss[0];
        double logZ = log(Z);
        out[0] = (float)idx;
        out[1] = (float)(1.0 / Z);
        out[2] = (float)(-logZ);
        out[3] = (float)(logZ - S1 / Z);
    }
}

// ---------------------------------------------------------------------------
extern "C" void kernel_launch(void* const* d_in, const int* in_sizes, int n_in,
                              void* d_out, int out_size)
{
    const float* x_graph = (const float*)d_in[0];
    const float* x_m     = (const float*)d_in[1];
    const float* x_job   = (const float*)d_in[2];
    const int*   m_ids   = (const int*)  d_in[3];
    const int*   job_idx = (const int*)  d_in[4];
    const float* W0      = (const float*)d_in[5];
    const float* b0      = (const float*)d_in[6];
    const float* W1      = (const float*)d_in[7];
    const float* b1      = (const float*)d_in[8];
    const float* W2      = (const float*)d_in[9];
    const float* b2      = (const float*)d_in[10];

    int n = in_sizes[3];
    int M = in_sizes[1] / HDIM;
    int J = in_sizes[2] / HDIM;
    int tiles = (n + TILE_OPS - 1) / TILE_OPS;
    int prep_blocks = M + J + 1 + 128;

    cudaFuncSetAttribute(kern_tile, cudaFuncAttributeMaxDynamicSharedMemorySize,
                         SMEM_TILE_TOTAL);

    kern_prep<<<prep_blocks, HDIM>>>(x_graph, x_m, x_job, W0, b0, W1, M, J);
    kern_tile<<<tiles, 256, SMEM_TILE_TOTAL>>>(m_ids, job_idx, b1, W2, b2, n);
    kern_reduce<<<1, RTH2>>>(tiles * 8, (float*)d_out);
}

// round 11
// speedup vs baseline: 1.8657x; 1.8657x over previous
#include <cuda_runtime.h>
#include <cuda_fp16.h>
#include <math.h>
#include <stdint.h>

#define HDIM 128
#define MAXM 1000
#define MAXJ 5000
#define MAXN 200000
#define TILE_OPS 128

#define RCHUNK 1024
#define RTH1   512
#define MAXP   512
#define RTH2   256

// ------------------------------ scratch ------------------------------------
__device__ __align__(16) float  g_g[HDIM];
__device__ __align__(16) __half g_Ah[MAXM * HDIM];   // fp16 A rows (incl. g)
__device__ __align__(16) __half g_Bh[MAXJ * HDIM];   // fp16 B rows
__device__ __align__(16) float  g_scores[MAXN];
__device__ float  g_pmax[MAXP];
__device__ int    g_pidx[MAXP];
__device__ double g_pZ[MAXP];
__device__ double g_pS1[MAXP];
// W1^T (rows = output h, cols = k), fp16, blocked-SW128 layout (32KB).
__device__ __align__(16) unsigned char g_W1T[32768];

// --------------------------- helpers ---------------------------------------
__device__ __forceinline__ uint32_t smem_u32(const void* p) {
    uint32_t a;
    asm("{ .reg .u64 t; cvta.to.shared.u64 t, %1; cvt.u32.u64 %0, t; }"
        : "=r"(a) : "l"(p));
    return a;
}

// swizzled byte offset in a 128row x 128col fp16 blocked-SW128 tile
__device__ __forceinline__ uint32_t tile_off(int row, int col) {
    uint32_t off = (uint32_t)(((row >> 3) + ((col >> 6) << 4)) * 1024
                              + (row & 7) * 128 + (col & 63) * 2);
    return off ^ ((off >> 3) & 0x70);
}

__device__ __forceinline__ void ldsm4(uint32_t* r, uint32_t addr) {
    asm volatile("ldmatrix.sync.aligned.m8n8.x4.shared.b16 {%0,%1,%2,%3}, [%4];"
                 : "=r"(r[0]), "=r"(r[1]), "=r"(r[2]), "=r"(r[3]) : "r"(addr));
}
__device__ __forceinline__ void mma_f16(float* d, const uint32_t* a,
                                        uint32_t b0, uint32_t b1) {
    asm volatile("mma.sync.aligned.m16n8k16.row.col.f32.f16.f16.f32 "
                 "{%0,%1,%2,%3}, {%4,%5,%6,%7}, {%8,%9}, {%0,%1,%2,%3};"
                 : "+f"(d[0]), "+f"(d[1]), "+f"(d[2]), "+f"(d[3])
                 : "r"(a[0]), "r"(a[1]), "r"(a[2]), "r"(a[3]), "r"(b0), "r"(b1));
}

// ---------------------------------------------------------------------------
// Kernel 0: g[h] = b0[h] + x_graph @ W0[:2H]
// ---------------------------------------------------------------------------
__global__ void kern_g(const float* __restrict__ x_graph,
                       const float* __restrict__ W0,
                       const float* __restrict__ b0)
{
    __shared__ float xs[2 * HDIM];
    int h = threadIdx.x;
    xs[h] = x_graph[h];
    xs[h + HDIM] = x_graph[h + HDIM];
    __syncthreads();
    float acc = b0[h];
    #pragma unroll 8
    for (int k = 0; k < 2 * HDIM; ++k)
        acc = fmaf(xs[k], W0[k * HDIM + h], acc);
    g_g[h] = acc;
}

// ---------------------------------------------------------------------------
// Kernel 1: A[m][h] = g[h] + x_m[m] @ W0[2H:3H];  B[j][h] = x_job[j] @ W0[3H:4H]
// fp32 accumulate, store fp16.
// ---------------------------------------------------------------------------
__global__ void kern_AB(const float* __restrict__ x_m,
                        const float* __restrict__ x_job,
                        const float* __restrict__ W0,
                        int M, int J)
{
    __shared__ float xs[HDIM];
    int h = threadIdx.x;
    int r = blockIdx.x;
    const float* src; const float* w; __half* dst; float acc;
    if (r < M) {
        src = x_m + (size_t)r * HDIM;
        w   = W0 + (size_t)(2 * HDIM) * HDIM;
        dst = g_Ah + (size_t)r * HDIM;
        acc = g_g[h];
    } else {
        int j = r - M;
        src = x_job + (size_t)j * HDIM;
        w   = W0 + (size_t)(3 * HDIM) * HDIM;
        dst = g_Bh + (size_t)j * HDIM;
        acc = 0.0f;
    }
    xs[h] = src[h];
    __syncthreads();
    #pragma unroll 8
    for (int k = 0; k < HDIM; ++k)
        acc = fmaf(xs[k], w[k * HDIM + h], acc);
    dst[h] = __float2half(acc);
}

// ---------------------------------------------------------------------------
// Kernel 1b: W1^T -> fp16 in blocked-SW128 layout.  Row r = output h, col c = k.
// ---------------------------------------------------------------------------
__global__ void kern_w1prep(const float* __restrict__ W1)
{
    int idx = blockIdx.x * blockDim.x + threadIdx.x;   // 0..16383
    int r = idx >> 7;
    int c = idx & 127;
    float w = W1[c * HDIM + r];
    *(__half*)(g_W1T + tile_off(r, c)) = __float2half(w);
}

// ---------------------------------------------------------------------------
// Kernel 2: fp16 HMMA tile kernel (R7, proven). 128 ops/block, 256 threads.
// Warp w computes op-rows [w*16, w*16+16) x all 128 output cols.
// D = h0 @ W1^T (fp32 accum); score[op] = b2 + sum_h relu(b1[h]+D[op][h])*W2[h]
// ---------------------------------------------------------------------------
#define OFF_A     0
#define OFF_W     32768
#define OFF_SB1   65536
#define OFF_SW2   66048
#define SMEM_TILE_TOTAL 66560

__global__ void __launch_bounds__(256, 2)
kern_tile(const int* __restrict__ m_ids,
          const int* __restrict__ job_idx,
          const float* __restrict__ b1,
          const float* __restrict__ W2,
          const float* __restrict__ b2,
          int n)
{
    extern __shared__ char smem[];
    uint32_t sb = smem_u32(smem);
    int tid = threadIdx.x;
    int wid = tid >> 5;
    int lid = tid & 31;
    int base = blockIdx.x * TILE_OPS;

    // ---- copy pre-swizzled W tile (32KB) ----
    {
        const uint4* src = (const uint4*)g_W1T;
        uint4* dst = (uint4*)(smem + OFF_W);
        #pragma unroll
        for (int i = 0; i < 8; ++i)
            dst[tid + 256 * i] = src[tid + 256 * i];
    }
    if (tid < HDIM) {
        ((float*)(smem + OFF_SB1))[tid] = b1[tid];
        ((float*)(smem + OFF_SW2))[tid] = W2[tid];
    }

    // ---- stage 1: gather h0 = relu(A[m]+B[j]) -> fp16 smem tile ----
    {
        int c0 = lid * 4;                 // this lane's 4 k-columns
        uint32_t colpart = (uint32_t)(((c0 >> 6) << 4) * 1024 + (c0 & 63) * 2);
        #pragma unroll 4
        for (int i = 0; i < 16; ++i) {
            int t = wid * 16 + i;
            int op = base + t;
            int m = 0, j = 0;
            if (op < n) { m = m_ids[op]; j = job_idx[op]; }
            uint2 ua = *(const uint2*)(g_Ah + m * HDIM + c0);
            uint2 ub = *(const uint2*)(g_Bh + j * HDIM + c0);
            float2 a0 = __half22float2(*(const half2*)&ua.x);
            float2 a1 = __half22float2(*(const half2*)&ua.y);
            float2 b0f = __half22float2(*(const half2*)&ub.x);
            float2 b1f = __half22float2(*(const half2*)&ub.y);
            float v0 = fmaxf(a0.x + b0f.x, 0.0f);
            float v1 = fmaxf(a0.y + b0f.y, 0.0f);
            float v2 = fmaxf(a1.x + b1f.x, 0.0f);
            float v3 = fmaxf(a1.y + b1f.y, 0.0f);
            half2 r0 = __floats2half2_rn(v0, v1);
            half2 r1 = __floats2half2_rn(v2, v3);
            uint32_t off = colpart + (uint32_t)(((t >> 3) << 10) + (t & 7) * 128);
            uint32_t sw = off ^ ((off >> 3) & 0x70);
            uint2 pv;
            pv.x = *(const uint32_t*)&r0;
            pv.y = *(const uint32_t*)&r1;
            *(uint2*)(smem + OFF_A + sw) = pv;
        }
    }
    __syncthreads();

    // ---- mainloop: 8 k-chunks x 8 n-pairs ----
    float d[16][4];
    #pragma unroll
    for (int nc = 0; nc < 16; ++nc)
        #pragma unroll
        for (int q = 0; q < 4; ++q) d[nc][q] = 0.0f;

    int arow = wid * 16 + (lid & 15);              // A-frag lane row
    int acolh = (lid >> 4) * 8;                    // A-frag lane k-offset
    int brow_in = ((lid >> 4) << 3) + (lid & 7);   // B-frag lane n-offset
    int bcol = ((lid >> 3) & 1) * 8;               // B-frag lane k-offset

    #pragma unroll
    for (int kc = 0; kc < 8; ++kc) {
        int kbase = kc * 16;
        uint32_t a[4];
        ldsm4(a, sb + OFF_A + tile_off(arow, kbase + acolh));
        #pragma unroll
        for (int np = 0; np < 8; ++np) {
            uint32_t b[4];
            ldsm4(b, sb + OFF_W + tile_off(np * 16 + brow_in, kbase + bcol));
            mma_f16(d[2 * np],     a, b[0], b[1]);
            mma_f16(d[2 * np + 1], a, b[2], b[3]);
        }
    }

    // ---- epilogue: relu(+b1)*W2, reduce over cols ----
    {
        const float* sb1 = (const float*)(smem + OFF_SB1);
        const float* sw2 = (const float*)(smem + OFF_SW2);
        int g = lid >> 2;
        int t4 = lid & 3;
        float s0 = 0.0f, s1 = 0.0f;
        #pragma unroll
        for (int nc = 0; nc < 16; ++nc) {
            int c0 = nc * 8 + 2 * t4;
            float bb0 = sb1[c0], bb1 = sb1[c0 + 1];
            float w0 = sw2[c0], w1 = sw2[c0 + 1];
            s0 = fmaf(fmaxf(d[nc][0] + bb0, 0.0f), w0, s0);
            s0 = fmaf(fmaxf(d[nc][1] + bb1, 0.0f), w1, s0);
            s1 = fmaf(fmaxf(d[nc][2] + bb0, 0.0f), w0, s1);
            s1 = fmaf(fmaxf(d[nc][3] + bb1, 0.0f), w1, s1);
        }
        unsigned mask = 0xffffffffu;
        s0 += __shfl_xor_sync(mask, s0, 1);
        s0 += __shfl_xor_sync(mask, s0, 2);
        s1 += __shfl_xor_sync(mask, s1, 1);
        s1 += __shfl_xor_sync(mask, s1, 2);
        if (t4 == 0) {
            float bias = b2[0];
            int op0 = base + wid * 16 + g;
            int op1 = op0 + 8;
            if (op0 < n) g_scores[op0] = s0 + bias;
            if (op1 < n) g_scores[op1] = s1 + bias;
        }
    }
}

// ---------------------------------------------------------------------------
// Kernel 3a: single-pass per-chunk softmax partials. 1024 scores/block,
// 512 threads; scores stay in registers between max and exp phases.
// ---------------------------------------------------------------------------
__global__ void __launch_bounds__(RTH1)
kern_reduce1(int n)
{
    __shared__ float  sv[RTH1];
    __shared__ int    si[RTH1];
    __shared__ double sz[RTH1];
    __shared__ double ss[RTH1];

    int tid = threadIdx.x;
    int b = blockIdx.x;
    int i0 = b * RCHUNK + 2 * tid;

    float v0 = -INFINITY, v1 = -INFINITY;
    if (i0 < n) {
        if (i0 + 1 < n) {
            float2 v = *(const float2*)(g_scores + i0);
            v0 = v.x; v1 = v.y;
        } else {
            v0 = g_scores[i0];
        }
    }

    // local max (i0 < i0+1: strict > keeps first occurrence)
    float best = v0; int bi = i0;
    if (v1 > best) { best = v1; bi = i0 + 1; }
    if (!(best > -INFINITY)) bi = 0x7fffffff;
    sv[tid] = best; si[tid] = bi;
    __syncthreads();
    #pragma unroll
    for (int s = RTH1 / 2; s > 0; s >>= 1) {
        if (tid < s) {
            float vo = sv[tid + s]; int io = si[tid + s];
            if (vo > sv[tid] || (vo == sv[tid] && io < si[tid])) {
                sv[tid] = vo; si[tid] = io;
            }
        }
        __syncthreads();
    }
    float mx = sv[0];
    int idx = si[0];
    __syncthreads();

    // exp on register copies; double tree for Z, S1
    double z = 0.0, s1d = 0.0;
    if (v0 > -INFINITY) {
        float t = v0 - mx;
        float e = expf(t);
        z += (double)e;
        s1d += (double)t * (double)e;
    }
    if (v1 > -INFINITY) {
        float t = v1 - mx;
        float e = expf(t);
        z += (double)e;
        s1d += (double)t * (double)e;
    }
    sz[tid] = z; ss[tid] = s1d;
    __syncthreads();
    #pragma unroll
    for (int s = RTH1 / 2; s > 0; s >>= 1) {
        if (tid < s) { sz[tid] += sz[tid + s]; ss[tid] += ss[tid + s]; }
        __syncthreads();
    }
    if (tid == 0) {
        g_pmax[b] = mx;
        g_pidx[b] = idx;
        g_pZ[b]   = sz[0];
        g_pS1[b]  = ss[0];
    }
}

// ---------------------------------------------------------------------------
// Kernel 3b: combine nblk partials (softmax-merge, fixed order)
// ---------------------------------------------------------------------------
__global__ void __launch_bounds__(RTH2)
kern_reduce2(int nblk, float* __restrict__ out)
{
    __shared__ float  sv[RTH2];
    __shared__ int    si[RTH2];
    __shared__ double sz[RTH2];
    __shared__ double ss[RTH2];

    int tid = threadIdx.x;

    float best = -INFINITY;
    int bi = 0x7fffffff;
    for (int i = tid; i < nblk; i += RTH2) {
        float v = g_pmax[i];
        int io = g_pidx[i];
        if (v > best || (v == best && io < bi)) { best = v; bi = io; }
    }
    sv[tid] = best; si[tid] = bi;
    __syncthreads();
    #pragma unroll
    for (int s = RTH2 / 2; s > 0; s >>= 1) {
        if (tid < s) {
            float vo = sv[tid + s]; int io = si[tid + s];
            if (vo > sv[tid] || (vo == sv[tid] && io < si[tid])) {
                sv[tid] = vo; si[tid] = io;
            }
        }
        __syncthreads();
    }
    float mx = sv[0];
    int idx = si[0];
    __syncthreads();

    double z = 0.0, s1 = 0.0;
    for (int i = tid; i < nblk; i += RTH2) {
        double zb = g_pZ[i];
        if (zb > 0.0) {
            double dd = (double)g_pmax[i] - (double)mx;
            double w = exp(dd);
            z  += w * zb;
            s1 += w * (g_pS1[i] + dd * zb);
        }
    }
    sz[tid] = z; ss[tid] = s1;
    __syncthreads();
    #pragma unroll
    for (int s = RTH2 / 2; s > 0; s >>= 1) {
        if (tid < s) { sz[tid] += sz[tid + s]; ss[tid] += ss[tid + s]; }
        __syncthreads();
    }
    if (tid == 0) {
        double Z = sz[0], S1 = ss[0];
        double logZ = log(Z);
        out[0] = (float)idx;
        out[1] = (float)(1.0 / Z);
        out[2] = (float)(-logZ);
        out[3] = (float)(logZ - S1 / Z);
    }
}

// ---------------------------------------------------------------------------
extern "C" void kernel_launch(void* const* d_in, const int* in_sizes, int n_in,
                              void* d_out, int out_size)
{
    const float* x_graph = (const float*)d_in[0];
    const float* x_m     = (const float*)d_in[1];
    const float* x_job   = (const float*)d_in[2];
    const int*   m_ids   = (const int*)  d_in[3];
    const int*   job_idx = (const int*)  d_in[4];
    const float* W0      = (const float*)d_in[5];
    const float* b0      = (const float*)d_in[6];
    const float* W1      = (const float*)d_in[7];
    const float* b1      = (const float*)d_in[8];
    const float* W2      = (const float*)d_in[9];
    const float* b2      = (const float*)d_in[10];

    int n = in_sizes[3];
    int M = in_sizes[1] / HDIM;
    int J = in_sizes[2] / HDIM;
    int tiles = (n + TILE_OPS - 1) / TILE_OPS;
    int rblks = (n + RCHUNK - 1) / RCHUNK;

    cudaFuncSetAttribute(kern_tile, cudaFuncAttributeMaxDynamicSharedMemorySize,
                         SMEM_TILE_TOTAL);

    kern_g<<<1, HDIM>>>(x_graph, W0, b0);
    kern_AB<<<M + J, HDIM>>>(x_m, x_job, W0, M, J);
    kern_w1prep<<<64, 256>>>(W1);
    kern_tile<<<tiles, 256, SMEM_TILE_TOTAL>>>(m_ids, job_idx, b1, W2, b2, n);
    kern_reduce1<<<rblks, RTH1>>>(n);
    kern_reduce2<<<1, RTH2>>>(rblks, (float*)d_out);
}

// round 12
// speedup vs baseline: 2.3034x; 1.2346x over previous
#include <cuda_runtime.h>
#include <cuda_fp16.h>
#include <math.h>
#include <stdint.h>

#define HDIM 128
#define MAXM 1000
#define MAXJ 5000
#define MAXN 200000
#define TILE_OPS 128

#define RCHUNK 1024
#define RTH1   512
#define MAXP   512
#define RTH2   256

// ------------------------------ scratch ------------------------------------
__device__ __align__(16) float  g_part[16 * HDIM];   // 16 k-partials of g
__device__ __align__(16) __half g_Ah[MAXM * HDIM];   // fp16 A rows (incl. g)
__device__ __align__(16) __half g_Bh[MAXJ * HDIM];   // fp16 B rows
__device__ __align__(16) float  g_scores[MAXN];
__device__ float  g_pmax[MAXP];
__device__ int    g_pidx[MAXP];
__device__ double g_pZ[MAXP];
__device__ double g_pS1[MAXP];
// W1^T (rows = output h, cols = k), fp16, blocked-SW128 layout (32KB).
__device__ __align__(16) unsigned char g_W1T[32768];

// --------------------------- helpers ---------------------------------------
__device__ __forceinline__ uint32_t smem_u32(const void* p) {
    uint32_t a;
    asm("{ .reg .u64 t; cvta.to.shared.u64 t, %1; cvt.u32.u64 %0, t; }"
        : "=r"(a) : "l"(p));
    return a;
}

// swizzled byte offset in a 128row x 128col fp16 blocked-SW128 tile
__device__ __forceinline__ uint32_t tile_off(int row, int col) {
    uint32_t off = (uint32_t)(((row >> 3) + ((col >> 6) << 4)) * 1024
                              + (row & 7) * 128 + (col & 63) * 2);
    return off ^ ((off >> 3) & 0x70);
}

__device__ __forceinline__ void ldsm4(uint32_t* r, uint32_t addr) {
    asm volatile("ldmatrix.sync.aligned.m8n8.x4.shared.b16 {%0,%1,%2,%3}, [%4];"
                 : "=r"(r[0]), "=r"(r[1]), "=r"(r[2]), "=r"(r[3]) : "r"(addr));
}
__device__ __forceinline__ void mma_f16(float* d, const uint32_t* a,
                                        uint32_t b0, uint32_t b1) {
    asm volatile("mma.sync.aligned.m16n8k16.row.col.f32.f16.f16.f32 "
                 "{%0,%1,%2,%3}, {%4,%5,%6,%7}, {%8,%9}, {%0,%1,%2,%3};"
                 : "+f"(d[0]), "+f"(d[1]), "+f"(d[2]), "+f"(d[3])
                 : "r"(a[0]), "r"(a[1]), "r"(a[2]), "r"(a[3]), "r"(b0), "r"(b1));
}

// ---------------------------------------------------------------------------
// Kernel P1: parallel prep stage 1.  128 threads/block.
//   blocks [0,16):    g_part[r][h] = (r==0 ? b0[h] : 0)
//                                     + sum_{k in [16r,16r+16)} x_graph[k]*W0[k][h]
//   blocks [16,144):  W1^T -> fp16 blocked-SW128
// ---------------------------------------------------------------------------
__global__ void __launch_bounds__(HDIM)
kern_prep1(const float* __restrict__ x_graph,
           const float* __restrict__ W0,
           const float* __restrict__ b0,
           const float* __restrict__ W1)
{
    int h = threadIdx.x;
    int r = blockIdx.x;
    if (r < 16) {
        __shared__ float xs[16];
        if (h < 16) xs[h] = x_graph[r * 16 + h];
        __syncthreads();
        float acc = (r == 0) ? b0[h] : 0.0f;
        #pragma unroll
        for (int k = 0; k < 16; ++k)
            acc = fmaf(xs[k], W0[(r * 16 + k) * HDIM + h], acc);
        g_part[r * HDIM + h] = acc;
    } else {
        int wb = r - 16;                       // 0..127
        int idx = wb * HDIM + h;               // 0..16383
        int rr = idx >> 7;
        int cc = idx & 127;
        float w = W1[cc * HDIM + rr];
        *(__half*)(g_W1T + tile_off(rr, cc)) = __float2half(w);
    }
}

// ---------------------------------------------------------------------------
// Kernel P2: A/B rows, 8 rows per block, 128 threads.
//   blocks [0, ablocks):          A rows 8*b ..        (adds g = sum g_part)
//   blocks [ablocks, ablocks+bblocks): B rows 8*(b-ablocks) ..
// smem stage is k-transposed (xsT[k][i]) so the inner loop reads one W0
// element and two broadcast LDS.128 per k.
// ---------------------------------------------------------------------------
__global__ void __launch_bounds__(HDIM)
kern_AB8(const float* __restrict__ x_m,
         const float* __restrict__ x_job,
         const float* __restrict__ W0,
         int M, int J, int ablocks)
{
    __shared__ __align__(16) float xsT[HDIM][8];
    int tid = threadIdx.x;
    int b = blockIdx.x;

    bool isA = (b < ablocks);
    int row0   = isA ? b * 8 : (b - ablocks) * 8;
    int nrows  = isA ? min(8, M - row0) : min(8, J - row0);
    const float* src = isA ? (x_m + (size_t)row0 * HDIM)
                           : (x_job + (size_t)row0 * HDIM);
    const float* w   = W0 + (size_t)((isA ? 2 : 3) * HDIM) * HDIM;
    __half* dst = (isA ? g_Ah : g_Bh) + (size_t)row0 * HDIM;

    // load rows -> transposed smem (each thread: 8 consecutive floats of row i)
    {
        int i = tid >> 4;                 // row 0..7
        int c0 = (tid & 15) * 8;          // col
        if (i < nrows) {
            float4 v0 = *(const float4*)(src + i * HDIM + c0);
            float4 v1 = *(const float4*)(src + i * HDIM + c0 + 4);
            xsT[c0 + 0][i] = v0.x; xsT[c0 + 1][i] = v0.y;
            xsT[c0 + 2][i] = v0.z; xsT[c0 + 3][i] = v0.w;
            xsT[c0 + 4][i] = v1.x; xsT[c0 + 5][i] = v1.y;
            xsT[c0 + 6][i] = v1.z; xsT[c0 + 7][i] = v1.w;
        } else {
            #pragma unroll
            for (int q = 0; q < 8; ++q) xsT[c0 + q][i] = 0.0f;
        }
    }
    __syncthreads();

    int h = tid;
    float acc[8];
    float ginit = 0.0f;
    if (isA) {
        #pragma unroll
        for (int p = 0; p < 16; ++p) ginit += g_part[p * HDIM + h];
    }
    #pragma unroll
    for (int i = 0; i < 8; ++i) acc[i] = ginit;

    #pragma unroll 4
    for (int k = 0; k < HDIM; ++k) {
        float wv = w[k * HDIM + h];
        const float4* xr = (const float4*)&xsT[k][0];
        float4 x0 = xr[0], x1 = xr[1];
        acc[0] = fmaf(x0.x, wv, acc[0]);
        acc[1] = fmaf(x0.y, wv, acc[1]);
        acc[2] = fmaf(x0.z, wv, acc[2]);
        acc[3] = fmaf(x0.w, wv, acc[3]);
        acc[4] = fmaf(x1.x, wv, acc[4]);
        acc[5] = fmaf(x1.y, wv, acc[5]);
        acc[6] = fmaf(x1.z, wv, acc[6]);
        acc[7] = fmaf(x1.w, wv, acc[7]);
    }
    #pragma unroll
    for (int i = 0; i < 8; ++i)
        if (i < nrows) dst[i * HDIM + h] = __float2half(acc[i]);
}

// ---------------------------------------------------------------------------
// Kernel 2: fp16 HMMA tile kernel (R7, proven, FROZEN). 128 ops/block,
// 256 threads.  Warp w computes op-rows [w*16, w*16+16) x all 128 cols.
// ---------------------------------------------------------------------------
#define OFF_A     0
#define OFF_W     32768
#define OFF_SB1   65536
#define OFF_SW2   66048
#define SMEM_TILE_TOTAL 66560

__global__ void __launch_bounds__(256, 2)
kern_tile(const int* __restrict__ m_ids,
          const int* __restrict__ job_idx,
          const float* __restrict__ b1,
          const float* __restrict__ W2,
          const float* __restrict__ b2,
          int n)
{
    extern __shared__ char smem[];
    uint32_t sb = smem_u32(smem);
    int tid = threadIdx.x;
    int wid = tid >> 5;
    int lid = tid & 31;
    int base = blockIdx.x * TILE_OPS;

    // ---- copy pre-swizzled W tile (32KB) ----
    {
        const uint4* src = (const uint4*)g_W1T;
        uint4* dst = (uint4*)(smem + OFF_W);
        #pragma unroll
        for (int i = 0; i < 8; ++i)
            dst[tid + 256 * i] = src[tid + 256 * i];
    }
    if (tid < HDIM) {
        ((float*)(smem + OFF_SB1))[tid] = b1[tid];
        ((float*)(smem + OFF_SW2))[tid] = W2[tid];
    }

    // ---- stage 1: gather h0 = relu(A[m]+B[j]) -> fp16 smem tile ----
    {
        int c0 = lid * 4;                 // this lane's 4 k-columns
        uint32_t colpart = (uint32_t)(((c0 >> 6) << 4) * 1024 + (c0 & 63) * 2);
        #pragma unroll 4
        for (int i = 0; i < 16; ++i) {
            int t = wid * 16 + i;
            int op = base + t;
            int m = 0, j = 0;
            if (op < n) { m = m_ids[op]; j = job_idx[op]; }
            uint2 ua = *(const uint2*)(g_Ah + m * HDIM + c0);
            uint2 ub = *(const uint2*)(g_Bh + j * HDIM + c0);
            float2 a0 = __half22float2(*(const half2*)&ua.x);
            float2 a1 = __half22float2(*(const half2*)&ua.y);
            float2 b0f = __half22float2(*(const half2*)&ub.x);
            float2 b1f = __half22float2(*(const half2*)&ub.y);
            float v0 = fmaxf(a0.x + b0f.x, 0.0f);
            float v1 = fmaxf(a0.y + b0f.y, 0.0f);
            float v2 = fmaxf(a1.x + b1f.x, 0.0f);
            float v3 = fmaxf(a1.y + b1f.y, 0.0f);
            half2 r0 = __floats2half2_rn(v0, v1);
            half2 r1 = __floats2half2_rn(v2, v3);
            uint32_t off = colpart + (uint32_t)(((t >> 3) << 10) + (t & 7) * 128);
            uint32_t sw = off ^ ((off >> 3) & 0x70);
            uint2 pv;
            pv.x = *(const uint32_t*)&r0;
            pv.y = *(const uint32_t*)&r1;
            *(uint2*)(smem + OFF_A + sw) = pv;
        }
    }
    __syncthreads();

    // ---- mainloop: 8 k-chunks x 8 n-pairs ----
    float d[16][4];
    #pragma unroll
    for (int nc = 0; nc < 16; ++nc)
        #pragma unroll
        for (int q = 0; q < 4; ++q) d[nc][q] = 0.0f;

    int arow = wid * 16 + (lid & 15);              // A-frag lane row
    int acolh = (lid >> 4) * 8;                    // A-frag lane k-offset
    int brow_in = ((lid >> 4) << 3) + (lid & 7);   // B-frag lane n-offset
    int bcol = ((lid >> 3) & 1) * 8;               // B-frag lane k-offset

    #pragma unroll
    for (int kc = 0; kc < 8; ++kc) {
        int kbase = kc * 16;
        uint32_t a[4];
        ldsm4(a, sb + OFF_A + tile_off(arow, kbase + acolh));
        #pragma unroll
        for (int np = 0; np < 8; ++np) {
            uint32_t b[4];
            ldsm4(b, sb + OFF_W + tile_off(np * 16 + brow_in, kbase + bcol));
            mma_f16(d[2 * np],     a, b[0], b[1]);
            mma_f16(d[2 * np + 1], a, b[2], b[3]);
        }
    }

    // ---- epilogue: relu(+b1)*W2, reduce over cols ----
    {
        const float* sb1 = (const float*)(smem + OFF_SB1);
        const float* sw2 = (const float*)(smem + OFF_SW2);
        int g = lid >> 2;
        int t4 = lid & 3;
        float s0 = 0.0f, s1 = 0.0f;
        #pragma unroll
        for (int nc = 0; nc < 16; ++nc) {
            int c0 = nc * 8 + 2 * t4;
            float bb0 = sb1[c0], bb1 = sb1[c0 + 1];
            float w0 = sw2[c0], w1 = sw2[c0 + 1];
            s0 = fmaf(fmaxf(d[nc][0] + bb0, 0.0f), w0, s0);
            s0 = fmaf(fmaxf(d[nc][1] + bb1, 0.0f), w1, s0);
            s1 = fmaf(fmaxf(d[nc][2] + bb0, 0.0f), w0, s1);
            s1 = fmaf(fmaxf(d[nc][3] + bb1, 0.0f), w1, s1);
        }
        unsigned mask = 0xffffffffu;
        s0 += __shfl_xor_sync(mask, s0, 1);
        s0 += __shfl_xor_sync(mask, s0, 2);
        s1 += __shfl_xor_sync(mask, s1, 1);
        s1 += __shfl_xor_sync(mask, s1, 2);
        if (t4 == 0) {
            float bias = b2[0];
            int op0 = base + wid * 16 + g;
            int op1 = op0 + 8;
            if (op0 < n) g_scores[op0] = s0 + bias;
            if (op1 < n) g_scores[op1] = s1 + bias;
        }
    }
}

// ---------------------------------------------------------------------------
// Kernel 3a: single-pass per-chunk softmax partials (R11, unchanged)
// ---------------------------------------------------------------------------
__global__ void __launch_bounds__(RTH1)
kern_reduce1(int n)
{
    __shared__ float  sv[RTH1];
    __shared__ int    si[RTH1];
    __shared__ double sz[RTH1];
    __shared__ double ss[RTH1];

    int tid = threadIdx.x;
    int b = blockIdx.x;
    int i0 = b * RCHUNK + 2 * tid;

    float v0 = -INFINITY, v1 = -INFINITY;
    if (i0 < n) {
        if (i0 + 1 < n) {
            float2 v = *(const float2*)(g_scores + i0);
            v0 = v.x; v1 = v.y;
        } else {
            v0 = g_scores[i0];
        }
    }

    float best = v0; int bi = i0;
    if (v1 > best) { best = v1; bi = i0 + 1; }
    if (!(best > -INFINITY)) bi = 0x7fffffff;
    sv[tid] = best; si[tid] = bi;
    __syncthreads();
    #pragma unroll
    for (int s = RTH1 / 2; s > 0; s >>= 1) {
        if (tid < s) {
            float vo = sv[tid + s]; int io = si[tid + s];
            if (vo > sv[tid] || (vo == sv[tid] && io < si[tid])) {
                sv[tid] = vo; si[tid] = io;
            }
        }
        __syncthreads();
    }
    float mx = sv[0];
    int idx = si[0];
    __syncthreads();

    double z = 0.0, s1d = 0.0;
    if (v0 > -INFINITY) {
        float t = v0 - mx;
        float e = expf(t);
        z += (double)e;
        s1d += (double)t * (double)e;
    }
    if (v1 > -INFINITY) {
        float t = v1 - mx;
        float e = expf(t);
        z += (double)e;
        s1d += (double)t * (double)e;
    }
    sz[tid] = z; ss[tid] = s1d;
    __syncthreads();
    #pragma unroll
    for (int s = RTH1 / 2; s > 0; s >>= 1) {
        if (tid < s) { sz[tid] += sz[tid + s]; ss[tid] += ss[tid + s]; }
        __syncthreads();
    }
    if (tid == 0) {
        g_pmax[b] = mx;
        g_pidx[b] = idx;
        g_pZ[b]   = sz[0];
        g_pS1[b]  = ss[0];
    }
}

// ---------------------------------------------------------------------------
// Kernel 3b: combine nblk partials (softmax-merge, fixed order)
// ---------------------------------------------------------------------------
__global__ void __launch_bounds__(RTH2)
kern_reduce2(int nblk, float* __restrict__ out)
{
    __shared__ float  sv[RTH2];
    __shared__ int    si[RTH2];
    __shared__ double sz[RTH2];
    __shared__ double ss[RTH2];

    int tid = threadIdx.x;

    float best = -INFINITY;
    int bi = 0x7fffffff;
    for (int i = tid; i < nblk; i += RTH2) {
        float v = g_pmax[i];
        int io = g_pidx[i];
        if (v > best || (v == best && io < bi)) { best = v; bi = io; }
    }
    sv[tid] = best; si[tid] = bi;
    __syncthreads();
    #pragma unroll
    for (int s = RTH2 / 2; s > 0; s >>= 1) {
        if (tid < s) {
            float vo = sv[tid + s]; int io = si[tid + s];
            if (vo > sv[tid] || (vo == sv[tid] && io < si[tid])) {
                sv[tid] = vo; si[tid] = io;
            }
        }
        __syncthreads();
    }
    float mx = sv[0];
    int idx = si[0];
    __syncthreads();

    double z = 0.0, s1 = 0.0;
    for (int i = tid; i < nblk; i += RTH2) {
        double zb = g_pZ[i];
        if (zb > 0.0) {
            double dd = (double)g_pmax[i] - (double)mx;
            double w = exp(dd);
            z  += w * zb;
            s1 += w * (g_pS1[i] + dd * zb);
        }
    }
    sz[tid] = z; ss[tid] = s1;
    __syncthreads();
    #pragma unroll
    for (int s = RTH2 / 2; s > 0; s >>= 1) {
        if (tid < s) { sz[tid] += sz[tid + s]; ss[tid] += ss[tid + s]; }
        __syncthreads();
    }
    if (tid == 0) {
        double Z = sz[0], S1 = ss[0];
        double logZ = log(Z);
        out[0] = (float)idx;
        out[1] = (float)(1.0 / Z);
        out[2] = (float)(-logZ);
        out[3] = (float)(logZ - S1 / Z);
    }
}

// ---------------------------------------------------------------------------
extern "C" void kernel_launch(void* const* d_in, const int* in_sizes, int n_in,
                              void* d_out, int out_size)
{
    const float* x_graph = (const float*)d_in[0];
    const float* x_m     = (const float*)d_in[1];
    const float* x_job   = (const float*)d_in[2];
    const int*   m_ids   = (const int*)  d_in[3];
    const int*   job_idx = (const int*)  d_in[4];
    const float* W0      = (const float*)d_in[5];
    const float* b0      = (const float*)d_in[6];
    const float* W1      = (const float*)d_in[7];
    const float* b1      = (const float*)d_in[8];
    const float* W2      = (const float*)d_in[9];
    const float* b2      = (const float*)d_in[10];

    int n = in_sizes[3];
    int M = in_sizes[1] / HDIM;
    int J = in_sizes[2] / HDIM;
    int tiles = (n + TILE_OPS - 1) / TILE_OPS;
    int rblks = (n + RCHUNK - 1) / RCHUNK;
    int ablocks = (M + 7) / 8;
    int bblocks = (J + 7) / 8;

    cudaFuncSetAttribute(kern_tile, cudaFuncAttributeMaxDynamicSharedMemorySize,
                         SMEM_TILE_TOTAL);

    kern_prep1<<<144, HDIM>>>(x_graph, W0, b0, W1);
    kern_AB8<<<ablocks + bblocks, HDIM>>>(x_m, x_job, W0, M, J, ablocks);
    kern_tile<<<tiles, 256, SMEM_TILE_TOTAL>>>(m_ids, job_idx, b1, W2, b2, n);
    kern_reduce1<<<rblks, RTH1>>>(n);
    kern_reduce2<<<1, RTH2>>>(rblks, (float*)d_out);
}

// round 13
// speedup vs baseline: 2.4457x; 1.0618x over previous
#include <cuda_runtime.h>
#include <cuda_fp16.h>
#include <math.h>
#include <stdint.h>

#define HDIM 128
#define MAXM 1000
#define MAXJ 5000
#define MAXN 200000
#define TILE_OPS 128

#define RCHUNK 2048
#define RTH1   512
#define MAXP   512
#define RTH2   128

// ------------------------------ scratch ------------------------------------
__device__ __align__(16) float  g_part[16 * HDIM];   // 16 k-partials of g
__device__ __align__(16) __half g_Ah[MAXM * HDIM];   // fp16 A rows (incl. g)
__device__ __align__(16) __half g_Bh[MAXJ * HDIM];   // fp16 B rows
__device__ __align__(16) float  g_scores[MAXN];
__device__ float  g_pmax[MAXP];
__device__ int    g_pidx[MAXP];
__device__ double g_pZ[MAXP];
__device__ double g_pS1[MAXP];
// W1^T (rows = output h, cols = k), fp16, blocked-SW128 layout (32KB).
__device__ __align__(16) unsigned char g_W1T[32768];

// --------------------------- helpers ---------------------------------------
__device__ __forceinline__ uint32_t smem_u32(const void* p) {
    uint32_t a;
    asm("{ .reg .u64 t; cvta.to.shared.u64 t, %1; cvt.u32.u64 %0, t; }"
        : "=r"(a) : "l"(p));
    return a;
}

// swizzled byte offset in a 128row x 128col fp16 blocked-SW128 tile
__device__ __forceinline__ uint32_t tile_off(int row, int col) {
    uint32_t off = (uint32_t)(((row >> 3) + ((col >> 6) << 4)) * 1024
                              + (row & 7) * 128 + (col & 63) * 2);
    return off ^ ((off >> 3) & 0x70);
}

__device__ __forceinline__ void ldsm4(uint32_t* r, uint32_t addr) {
    asm volatile("ldmatrix.sync.aligned.m8n8.x4.shared.b16 {%0,%1,%2,%3}, [%4];"
                 : "=r"(r[0]), "=r"(r[1]), "=r"(r[2]), "=r"(r[3]) : "r"(addr));
}
__device__ __forceinline__ void mma_f16(float* d, const uint32_t* a,
                                        uint32_t b0, uint32_t b1) {
    asm volatile("mma.sync.aligned.m16n8k16.row.col.f32.f16.f16.f32 "
                 "{%0,%1,%2,%3}, {%4,%5,%6,%7}, {%8,%9}, {%0,%1,%2,%3};"
                 : "+f"(d[0]), "+f"(d[1]), "+f"(d[2]), "+f"(d[3])
                 : "r"(a[0]), "r"(a[1]), "r"(a[2]), "r"(a[3]), "r"(b0), "r"(b1));
}

// warp argmax merge step
__device__ __forceinline__ void wmerge(float& v, int& bi, unsigned mask, int off) {
    float vo = __shfl_xor_sync(mask, v, off);
    int io = __shfl_xor_sync(mask, bi, off);
    if (vo > v || (vo == v && io < bi)) { v = vo; bi = io; }
}

// ---------------------------------------------------------------------------
// Kernel P1: parallel prep stage 1.  128 threads/block.
//   blocks [0,16):    g_part[r][h] = (r==0 ? b0[h] : 0) + partial x_graph@W0
//   blocks [16,144):  W1^T -> fp16 blocked-SW128
// ---------------------------------------------------------------------------
__global__ void __launch_bounds__(HDIM)
kern_prep1(const float* __restrict__ x_graph,
           const float* __restrict__ W0,
           const float* __restrict__ b0,
           const float* __restrict__ W1)
{
    int h = threadIdx.x;
    int r = blockIdx.x;
    if (r < 16) {
        __shared__ float xs[16];
        if (h < 16) xs[h] = x_graph[r * 16 + h];
        __syncthreads();
        float acc = (r == 0) ? b0[h] : 0.0f;
        #pragma unroll
        for (int k = 0; k < 16; ++k)
            acc = fmaf(xs[k], W0[(r * 16 + k) * HDIM + h], acc);
        g_part[r * HDIM + h] = acc;
    } else {
        int wb = r - 16;                       // 0..127
        int idx = wb * HDIM + h;               // 0..16383
        int rr = idx >> 7;
        int cc = idx & 127;
        float w = W1[cc * HDIM + rr];
        *(__half*)(g_W1T + tile_off(rr, cc)) = __float2half(w);
    }
}

// ---------------------------------------------------------------------------
// Kernel P2: A/B rows, 8 rows per block, 128 threads (R12, proven).
// ---------------------------------------------------------------------------
__global__ void __launch_bounds__(HDIM)
kern_AB8(const float* __restrict__ x_m,
         const float* __restrict__ x_job,
         const float* __restrict__ W0,
         int M, int J, int ablocks)
{
    __shared__ __align__(16) float xsT[HDIM][8];
    int tid = threadIdx.x;
    int b = blockIdx.x;

    bool isA = (b < ablocks);
    int row0   = isA ? b * 8 : (b - ablocks) * 8;
    int nrows  = isA ? min(8, M - row0) : min(8, J - row0);
    const float* src = isA ? (x_m + (size_t)row0 * HDIM)
                           : (x_job + (size_t)row0 * HDIM);
    const float* w   = W0 + (size_t)((isA ? 2 : 3) * HDIM) * HDIM;
    __half* dst = (isA ? g_Ah : g_Bh) + (size_t)row0 * HDIM;

    {
        int i = tid >> 4;                 // row 0..7
        int c0 = (tid & 15) * 8;          // col
        if (i < nrows) {
            float4 v0 = *(const float4*)(src + i * HDIM + c0);
            float4 v1 = *(const float4*)(src + i * HDIM + c0 + 4);
            xsT[c0 + 0][i] = v0.x; xsT[c0 + 1][i] = v0.y;
            xsT[c0 + 2][i] = v0.z; xsT[c0 + 3][i] = v0.w;
            xsT[c0 + 4][i] = v1.x; xsT[c0 + 5][i] = v1.y;
            xsT[c0 + 6][i] = v1.z; xsT[c0 + 7][i] = v1.w;
        } else {
            #pragma unroll
            for (int q = 0; q < 8; ++q) xsT[c0 + q][i] = 0.0f;
        }
    }
    __syncthreads();

    int h = tid;
    float acc[8];
    float ginit = 0.0f;
    if (isA) {
        #pragma unroll
        for (int p = 0; p < 16; ++p) ginit += g_part[p * HDIM + h];
    }
    #pragma unroll
    for (int i = 0; i < 8; ++i) acc[i] = ginit;

    #pragma unroll 4
    for (int k = 0; k < HDIM; ++k) {
        float wv = w[k * HDIM + h];
        const float4* xr = (const float4*)&xsT[k][0];
        float4 x0 = xr[0], x1 = xr[1];
        acc[0] = fmaf(x0.x, wv, acc[0]);
        acc[1] = fmaf(x0.y, wv, acc[1]);
        acc[2] = fmaf(x0.z, wv, acc[2]);
        acc[3] = fmaf(x0.w, wv, acc[3]);
        acc[4] = fmaf(x1.x, wv, acc[4]);
        acc[5] = fmaf(x1.y, wv, acc[5]);
        acc[6] = fmaf(x1.z, wv, acc[6]);
        acc[7] = fmaf(x1.w, wv, acc[7]);
    }
    #pragma unroll
    for (int i = 0; i < 8; ++i)
        if (i < nrows) dst[i * HDIM + h] = __float2half(acc[i]);
}

// ---------------------------------------------------------------------------
// Kernel 2: fp16 HMMA tile kernel (R7, proven, FROZEN).
// ---------------------------------------------------------------------------
#define OFF_A     0
#define OFF_W     32768
#define OFF_SB1   65536
#define OFF_SW2   66048
#define SMEM_TILE_TOTAL 66560

__global__ void __launch_bounds__(256, 2)
kern_tile(const int* __restrict__ m_ids,
          const int* __restrict__ job_idx,
          const float* __restrict__ b1,
          const float* __restrict__ W2,
          const float* __restrict__ b2,
          int n)
{
    extern __shared__ char smem[];
    uint32_t sb = smem_u32(smem);
    int tid = threadIdx.x;
    int wid = tid >> 5;
    int lid = tid & 31;
    int base = blockIdx.x * TILE_OPS;

    {
        const uint4* src = (const uint4*)g_W1T;
        uint4* dst = (uint4*)(smem + OFF_W);
        #pragma unroll
        for (int i = 0; i < 8; ++i)
            dst[tid + 256 * i] = src[tid + 256 * i];
    }
    if (tid < HDIM) {
        ((float*)(smem + OFF_SB1))[tid] = b1[tid];
        ((float*)(smem + OFF_SW2))[tid] = W2[tid];
    }

    {
        int c0 = lid * 4;
        uint32_t colpart = (uint32_t)(((c0 >> 6) << 4) * 1024 + (c0 & 63) * 2);
        #pragma unroll 4
        for (int i = 0; i < 16; ++i) {
            int t = wid * 16 + i;
            int op = base + t;
            int m = 0, j = 0;
            if (op < n) { m = m_ids[op]; j = job_idx[op]; }
            uint2 ua = *(const uint2*)(g_Ah + m * HDIM + c0);
            uint2 ub = *(const uint2*)(g_Bh + j * HDIM + c0);
            float2 a0 = __half22float2(*(const half2*)&ua.x);
            float2 a1 = __half22float2(*(const half2*)&ua.y);
            float2 b0f = __half22float2(*(const half2*)&ub.x);
            float2 b1f = __half22float2(*(const half2*)&ub.y);
            float v0 = fmaxf(a0.x + b0f.x, 0.0f);
            float v1 = fmaxf(a0.y + b0f.y, 0.0f);
            float v2 = fmaxf(a1.x + b1f.x, 0.0f);
            float v3 = fmaxf(a1.y + b1f.y, 0.0f);
            half2 r0 = __floats2half2_rn(v0, v1);
            half2 r1 = __floats2half2_rn(v2, v3);
            uint32_t off = colpart + (uint32_t)(((t >> 3) << 10) + (t & 7) * 128);
            uint32_t sw = off ^ ((off >> 3) & 0x70);
            uint2 pv;
            pv.x = *(const uint32_t*)&r0;
            pv.y = *(const uint32_t*)&r1;
            *(uint2*)(smem + OFF_A + sw) = pv;
        }
    }
    __syncthreads();

    float d[16][4];
    #pragma unroll
    for (int nc = 0; nc < 16; ++nc)
        #pragma unroll
        for (int q = 0; q < 4; ++q) d[nc][q] = 0.0f;

    int arow = wid * 16 + (lid & 15);
    int acolh = (lid >> 4) * 8;
    int brow_in = ((lid >> 4) << 3) + (lid & 7);
    int bcol = ((lid >> 3) & 1) * 8;

    #pragma unroll
    for (int kc = 0; kc < 8; ++kc) {
        int kbase = kc * 16;
        uint32_t a[4];
        ldsm4(a, sb + OFF_A + tile_off(arow, kbase + acolh));
        #pragma unroll
        for (int np = 0; np < 8; ++np) {
            uint32_t b[4];
            ldsm4(b, sb + OFF_W + tile_off(np * 16 + brow_in, kbase + bcol));
            mma_f16(d[2 * np],     a, b[0], b[1]);
            mma_f16(d[2 * np + 1], a, b[2], b[3]);
        }
    }

    {
        const float* sb1 = (const float*)(smem + OFF_SB1);
        const float* sw2 = (const float*)(smem + OFF_SW2);
        int g = lid >> 2;
        int t4 = lid & 3;
        float s0 = 0.0f, s1 = 0.0f;
        #pragma unroll
        for (int nc = 0; nc < 16; ++nc) {
            int c0 = nc * 8 + 2 * t4;
            float bb0 = sb1[c0], bb1 = sb1[c0 + 1];
            float w0 = sw2[c0], w1 = sw2[c0 + 1];
            s0 = fmaf(fmaxf(d[nc][0] + bb0, 0.0f), w0, s0);
            s0 = fmaf(fmaxf(d[nc][1] + bb1, 0.0f), w1, s0);
            s1 = fmaf(fmaxf(d[nc][2] + bb0, 0.0f), w0, s1);
            s1 = fmaf(fmaxf(d[nc][3] + bb1, 0.0f), w1, s1);
        }
        unsigned mask = 0xffffffffu;
        s0 += __shfl_xor_sync(mask, s0, 1);
        s0 += __shfl_xor_sync(mask, s0, 2);
        s1 += __shfl_xor_sync(mask, s1, 1);
        s1 += __shfl_xor_sync(mask, s1, 2);
        if (t4 == 0) {
            float bias = b2[0];
            int op0 = base + wid * 16 + g;
            int op1 = op0 + 8;
            if (op0 < n) g_scores[op0] = s0 + bias;
            if (op1 < n) g_scores[op1] = s1 + bias;
        }
    }
}

// ---------------------------------------------------------------------------
// Kernel 3a: per-chunk softmax partials, shuffle-based (3 barriers total).
// 2048 scores/block, 512 threads, 4 scores/thread in registers.
// ---------------------------------------------------------------------------
__global__ void __launch_bounds__(RTH1)
kern_reduce1(int n)
{
    __shared__ float  wv_s[16];
    __shared__ int    wi_s[16];
    __shared__ double wz_s[16];
    __shared__ double ws_s[16];
    __shared__ float  mx_s;
    __shared__ int    idx_s;

    int tid = threadIdx.x;
    int lid = tid & 31;
    int wrp = tid >> 5;
    int b = blockIdx.x;
    int i0 = b * RCHUNK + tid * 4;
    unsigned mask = 0xffffffffu;

    float v[4] = { -INFINITY, -INFINITY, -INFINITY, -INFINITY };
    if (i0 + 3 < n) {
        float4 q = *(const float4*)(g_scores + i0);
        v[0] = q.x; v[1] = q.y; v[2] = q.z; v[3] = q.w;
    } else {
        #pragma unroll
        for (int q = 0; q < 4; ++q)
            if (i0 + q < n) v[q] = g_scores[i0 + q];
    }

    // thread-local argmax (ascending index, strict > keeps first)
    float best = v[0]; int bi = i0;
    #pragma unroll
    for (int q = 1; q < 4; ++q)
        if (v[q] > best) { best = v[q]; bi = i0 + q; }
    if (!(best > -INFINITY)) bi = 0x7fffffff;

    // warp butterfly argmax
    wmerge(best, bi, mask, 16);
    wmerge(best, bi, mask, 8);
    wmerge(best, bi, mask, 4);
    wmerge(best, bi, mask, 2);
    wmerge(best, bi, mask, 1);
    if (lid == 0) { wv_s[wrp] = best; wi_s[wrp] = bi; }
    __syncthreads();

    if (wrp == 0) {
        float vv = (lid < 16) ? wv_s[lid] : -INFINITY;
        int ii = (lid < 16) ? wi_s[lid] : 0x7fffffff;
        wmerge(vv, ii, mask, 8);
        wmerge(vv, ii, mask, 4);
        wmerge(vv, ii, mask, 2);
        wmerge(vv, ii, mask, 1);
        if (lid == 0) { mx_s = vv; idx_s = ii; }
    }
    __syncthreads();
    float mx = mx_s;

    // exp phase on register copies
    double z = 0.0, s1d = 0.0;
    #pragma unroll
    for (int q = 0; q < 4; ++q) {
        if (v[q] > -INFINITY) {
            float t = v[q] - mx;
            float e = expf(t);
            z += (double)e;
            s1d += (double)t * (double)e;
        }
    }
    #pragma unroll
    for (int off = 16; off > 0; off >>= 1) {
        z   += __shfl_xor_sync(mask, z, off);
        s1d += __shfl_xor_sync(mask, s1d, off);
    }
    if (lid == 0) { wz_s[wrp] = z; ws_s[wrp] = s1d; }
    __syncthreads();

    if (wrp == 0) {
        double zz = (lid < 16) ? wz_s[lid] : 0.0;
        double ssv = (lid < 16) ? ws_s[lid] : 0.0;
        #pragma unroll
        for (int off = 8; off > 0; off >>= 1) {
            zz  += __shfl_xor_sync(mask, zz, off);
            ssv += __shfl_xor_sync(mask, ssv, off);
        }
        if (lid == 0) {
            g_pmax[b] = mx;
            g_pidx[b] = idx_s;
            g_pZ[b]   = zz;
            g_pS1[b]  = ssv;
        }
    }
}

// ---------------------------------------------------------------------------
// Kernel 3b: combine nblk (<=128) partials, shuffle-based.
// ---------------------------------------------------------------------------
__global__ void __launch_bounds__(RTH2)
kern_reduce2(int nblk, float* __restrict__ out)
{
    __shared__ float  wv_s[4];
    __shared__ int    wi_s[4];
    __shared__ double wz_s[4];
    __shared__ double ws_s[4];
    __shared__ float  mx_s;
    __shared__ int    idx_s;

    int tid = threadIdx.x;
    int lid = tid & 31;
    int wrp = tid >> 5;
    unsigned mask = 0xffffffffu;

    float best = (tid < nblk) ? g_pmax[tid] : -INFINITY;
    int bi = (tid < nblk) ? g_pidx[tid] : 0x7fffffff;

    wmerge(best, bi, mask, 16);
    wmerge(best, bi, mask, 8);
    wmerge(best, bi, mask, 4);
    wmerge(best, bi, mask, 2);
    wmerge(best, bi, mask, 1);
    if (lid == 0) { wv_s[wrp] = best; wi_s[wrp] = bi; }
    __syncthreads();

    if (wrp == 0) {
        float vv = (lid < 4) ? wv_s[lid] : -INFINITY;
        int ii = (lid < 4) ? wi_s[lid] : 0x7fffffff;
        wmerge(vv, ii, mask, 2);
        wmerge(vv, ii, mask, 1);
        if (lid == 0) { mx_s = vv; idx_s = ii; }
    }
    __syncthreads();
    float mx = mx_s;

    double z = 0.0, s1 = 0.0;
    if (tid < nblk) {
        double zb = g_pZ[tid];
        if (zb > 0.0) {
            double dd = (double)g_pmax[tid] - (double)mx;
            double w = exp(dd);
            z  = w * zb;
            s1 = w * (g_pS1[tid] + dd * zb);
        }
    }
    #pragma unroll
    for (int off = 16; off > 0; off >>= 1) {
        z  += __shfl_xor_sync(mask, z, off);
        s1 += __shfl_xor_sync(mask, s1, off);
    }
    if (lid == 0) { wz_s[wrp] = z; ws_s[wrp] = s1; }
    __syncthreads();

    if (tid == 0) {
        double Z = wz_s[0] + wz_s[1] + wz_s[2] + wz_s[3];
        double S1 = ws_s[0] + ws_s[1] + ws_s[2] + ws_s[3];
        double logZ = log(Z);
        out[0] = (float)idx_s;
        out[1] = (float)(1.0 / Z);
        out[2] = (float)(-logZ);
        out[3] = (float)(logZ - S1 / Z);
    }
}

// ---------------------------------------------------------------------------
extern "C" void kernel_launch(void* const* d_in, const int* in_sizes, int n_in,
                              void* d_out, int out_size)
{
    const float* x_graph = (const float*)d_in[0];
    const float* x_m     = (const float*)d_in[1];
    const float* x_job   = (const float*)d_in[2];
    const int*   m_ids   = (const int*)  d_in[3];
    const int*   job_idx = (const int*)  d_in[4];
    const float* W0      = (const float*)d_in[5];
    const float* b0      = (const float*)d_in[6];
    const float* W1      = (const float*)d_in[7];
    const float* b1      = (const float*)d_in[8];
    const float* W2      = (const float*)d_in[9];
    const float* b2      = (const float*)d_in[10];

    int n = in_sizes[3];
    int M = in_sizes[1] / HDIM;
    int J = in_sizes[2] / HDIM;
    int tiles = (n + TILE_OPS - 1) / TILE_OPS;
    int rblks = (n + RCHUNK - 1) / RCHUNK;
    int ablocks = (M + 7) / 8;
    int bblocks = (J + 7) / 8;

    cudaFuncSetAttribute(kern_tile, cudaFuncAttributeMaxDynamicSharedMemorySize,
                         SMEM_TILE_TOTAL);

    kern_prep1<<<144, HDIM>>>(x_graph, W0, b0, W1);
    kern_AB8<<<ablocks + bblocks, HDIM>>>(x_m, x_job, W0, M, J, ablocks);
    kern_tile<<<tiles, 256, SMEM_TILE_TOTAL>>>(m_ids, job_idx, b1, W2, b2, n);
    kern_reduce1<<<rblks, RTH1>>>(n);
    kern_reduce2<<<1, RTH2>>>(rblks, (float*)d_out);
}